// round 4
// baseline (speedup 1.0000x reference)
#include <cuda_runtime.h>
#include <cuda_bf16.h>
#include <cstdint>

#define NROWS 20736
#define DIMX 1024
#define HIDX 4096
#define KIN  3072
typedef signed char s8;

// ---------------- scratch (device globals; no allocs) ----------------
__device__ __align__(16) s8 g_A0a[(size_t)NROWS * KIN];
__device__ __align__(16) s8 g_A0b[(size_t)NROWS * KIN];
__device__ __align__(16) s8 g_ha[(size_t)NROWS * DIMX];
__device__ __align__(16) s8 g_hb[(size_t)NROWS * DIMX];
__device__ __align__(16) s8 g_ua[(size_t)NROWS * HIDX];
__device__ __align__(16) s8 g_ub[(size_t)NROWS * HIDX];
__device__ __align__(16) float g_h[(size_t)NROWS * DIMX];
__device__ __align__(16) float g_u[(size_t)NROWS * HIDX];

__device__ __align__(16) s8 g_wq_in[DIMX * KIN];
__device__ __align__(16) s8 g_wq1[2 * HIDX * DIMX];
__device__ __align__(16) s8 g_wq2[2 * DIMX * HIDX];
__device__ __align__(16) s8 g_wqz[DIMX * DIMX];
__device__ __align__(16) s8 g_wqm[DIMX];

__device__ unsigned g_rmax[6][NROWS];
__device__ float g_s[6][NROWS];
__device__ float g_sinv[6][NROWS];
#define NPART 512
__device__ double g_part[8][NPART];
__device__ float g_scale[8];

// ---------------- small helpers ----------------
__device__ __forceinline__ uint32_t smem_u32(const void* p) {
    uint32_t a;
    asm("{ .reg .u64 t; cvta.to.shared.u64 t, %1; cvt.u32.u64 %0, t; }" : "=r"(a) : "l"(p));
    return a;
}
__device__ __forceinline__ void cpa16(uint32_t dst, const void* src) {
    asm volatile("cp.async.cg.shared.global [%0], [%1], 16;\n" ::"r"(dst), "l"(src));
}
__device__ __forceinline__ float gelu_f(float x) {
    return 0.5f * x * (1.0f + erff(x * 0.70710678118654752f));
}

#define LDSM4(r0, r1, r2, r3, a) \
    asm volatile("ldmatrix.sync.aligned.m8n8.x4.shared.b16 {%0,%1,%2,%3}, [%4];" \
        : "=r"(r0), "=r"(r1), "=r"(r2), "=r"(r3) : "r"(a))

#define IMMA(c, a, b) \
    asm volatile("mma.sync.aligned.m16n8k32.row.col.s32.s8.s8.s32 " \
        "{%0,%1,%2,%3},{%4,%5,%6,%7},{%8,%9},{%0,%1,%2,%3};" \
        : "+r"((c)[0]), "+r"((c)[1]), "+r"((c)[2]), "+r"((c)[3]) \
        : "r"((a)[0]), "r"((a)[1]), "r"((a)[2]), "r"((a)[3]), "r"((b)[0]), "r"((b)[1]))

// ---------------- prep kernels ----------------
__global__ void k_zero() {
    int n = 6 * NROWS;
    for (int i = blockIdx.x * 256 + threadIdx.x; i < n; i += gridDim.x * 256)
        ((unsigned*)g_rmax)[i] = 0u;
}

struct P7 { const float* w[7]; long n[7]; };
struct Q7 { const float* w[7]; s8* q[7]; long n[7]; };

__global__ void k_abssum7(P7 p) {
    int t = blockIdx.y;
    const float* __restrict__ w = p.w[t];
    long n = p.n[t];
    double s = 0.0;
    for (long i = (long)blockIdx.x * blockDim.x + threadIdx.x; i < n;
         i += (long)gridDim.x * blockDim.x)
        s += fabs((double)w[i]);
    __shared__ double sh[256];
    sh[threadIdx.x] = s;
    __syncthreads();
    for (int o = 128; o > 0; o >>= 1) {
        if (threadIdx.x < o) sh[threadIdx.x] += sh[threadIdx.x + o];
        __syncthreads();
    }
    if (threadIdx.x == 0) g_part[t][blockIdx.x] = sh[0];
}

__global__ void k_finalize() {
    int i = threadIdx.x;
    if (i >= 7) return;
    const double cnt[7] = {3145728.0, 4194304.0, 4194304.0, 4194304.0,
                           4194304.0, 1048576.0, 1024.0};
    double s = 0.0;
    for (int j = 0; j < NPART; j++) s += g_part[i][j];
    g_scale[i] = (float)(s / cnt[i]) + 1e-8f;
}

__global__ void k_quant7(Q7 p) {
    int t = blockIdx.y;
    const float* __restrict__ w = p.w[t];
    s8* __restrict__ q = p.q[t];
    long n = p.n[t];
    float a = g_scale[t];
    for (long i = (long)blockIdx.x * blockDim.x + threadIdx.x; i < n;
         i += (long)gridDim.x * blockDim.x) {
        float v = rintf(w[i] / a);
        v = fminf(1.0f, fmaxf(-1.0f, v));
        q[i] = (s8)(int)v;
    }
}

// concat x|y|s -> per-row max -> int8 hi/lo split (stage 0)
__global__ void k_build_a0(const float* __restrict__ x, const float* __restrict__ y,
                           const float* __restrict__ sp) {
    int row = blockIdx.x, tid = threadIdx.x;
    float v[12];
    float m = 0.0f;
#pragma unroll
    for (int i = 0; i < 12; i++) {
        int c = tid + i * 256;
        const float* s = (c < DIMX) ? x : (c < 2 * DIMX) ? y : sp;
        v[i] = s[(size_t)row * DIMX + (c & 1023)];
        m = fmaxf(m, fabsf(v[i]));
    }
    __shared__ float sm[256];
    sm[tid] = m;
    __syncthreads();
    for (int o = 128; o > 0; o >>= 1) {
        if (tid < o) sm[tid] = fmaxf(sm[tid], sm[tid + o]);
        __syncthreads();
    }
    float mx = sm[0];
    float si = mx > 0.0f ? 8128.0f / mx : 0.0f;
    if (tid == 0) {
        g_s[0][row] = mx * (1.0f / 8128.0f);
        g_sinv[0][row] = si;
    }
#pragma unroll
    for (int i = 0; i < 12; i++) {
        int c = tid + i * 256;
        float n = rintf(v[i] * si);
        n = fminf(8128.0f, fmaxf(-8128.0f, n));
        float a = rintf(n * (1.0f / 64.0f));
        float b = n - 64.0f * a;
        size_t o = (size_t)row * KIN + c;
        g_A0a[o] = (s8)(int)a;
        g_A0b[o] = (s8)(int)b;
    }
}

__global__ void k_rowscale(int st) {
    int i = blockIdx.x * 256 + threadIdx.x;
    if (i >= NROWS) return;
    float m = __uint_as_float(g_rmax[st][i]);
    g_s[st][i] = m * (1.0f / 8128.0f);
    g_sinv[st][i] = m > 0.0f ? 8128.0f / m : 0.0f;
}

__global__ void k_quantact(const float* __restrict__ act, int st, int cshift,
                           s8* __restrict__ qa, s8* __restrict__ qb, size_t total) {
    for (size_t i = (size_t)blockIdx.x * blockDim.x + threadIdx.x; i < total;
         i += (size_t)gridDim.x * blockDim.x) {
        size_t row = i >> cshift;
        float si = g_sinv[st][row];
        float n = rintf(act[i] * si);
        n = fminf(8128.0f, fmaxf(-8128.0f, n));
        float a = rintf(n * (1.0f / 64.0f));
        float b = n - 64.0f * a;
        qa[i] = (s8)(int)a;
        qb[i] = (s8)(int)b;
    }
}

// ---------------- int8 GEMM: 128x128 tile, K-chunk 64, hi/lo into one s32 acc ----------------
enum { EPI_H = 0, EPI_GELU = 1, EPI_RES = 2, EPI_Z = 3 };
#define STG 30720  // Aa(10240) + Ab(10240) + Bt(10240), 80B pitch

__device__ __forceinline__ void ld_stage(uint32_t sb, const s8* __restrict__ Aa,
                                         const s8* __restrict__ Ab,
                                         const s8* __restrict__ Bw,
                                         int K, int bm, int bn, int chunk, int tid) {
    int k0 = chunk * 64;
#pragma unroll
    for (int i = 0; i < 2; i++) {
        int j = tid + i * 256;
        int r = j >> 2, c = (j & 3) * 16;
        uint32_t d = sb + r * 80 + c;
        cpa16(d,         Aa + (size_t)(bm + r) * K + k0 + c);
        cpa16(d + 10240, Ab + (size_t)(bm + r) * K + k0 + c);
        cpa16(d + 20480, Bw + (size_t)(bn + r) * K + k0 + c);
    }
}

template <int EPI>
__global__ void __launch_bounds__(256, 2)
k_igemm(const s8* __restrict__ Aa, const s8* __restrict__ Ab,
        const s8* __restrict__ Bw, int K, const float* __restrict__ bias,
        int sidx, int stIn, int stOut, int Ncols,
        float* __restrict__ ActOut, float* __restrict__ Zout) {
    extern __shared__ char dsm[];
    __shared__ unsigned s_rm[128];
    uint32_t base = smem_u32(dsm);
    const int tid = threadIdx.x, lane = tid & 31, wid = tid >> 5;
    const int bm = blockIdx.y * 128, bn = blockIdx.x * 128;
    const int wm = (wid >> 2) * 64, wn = (wid & 3) * 32;
    const int KT = K / 64;

    int acc[4][4][4];
#pragma unroll
    for (int i = 0; i < 4; i++)
#pragma unroll
        for (int j = 0; j < 4; j++)
#pragma unroll
            for (int k = 0; k < 4; k++) acc[i][j][k] = 0;

    ld_stage(base, Aa, Ab, Bw, K, bm, bn, 0, tid);
    asm volatile("cp.async.commit_group;\n");

    for (int kt = 0; kt < KT; kt++) {
        int buf = kt & 1;
        uint32_t sb = base + buf * STG;
        if (kt + 1 < KT) ld_stage(base + (buf ^ 1) * STG, Aa, Ab, Bw, K, bm, bn, kt + 1, tid);
        asm volatile("cp.async.commit_group;\n");
        asm volatile("cp.async.wait_group 1;\n" ::: "memory");
        __syncthreads();
#pragma unroll
        for (int ks = 0; ks < 2; ks++) {
            uint32_t bt[4][2], bh[4][2], af[4][4];
#pragma unroll
            for (int nh = 0; nh < 2; nh++) {
                uint32_t a = sb + 20480 + (wn + nh * 16 + (lane & 15)) * 80 +
                             ks * 32 + ((lane >> 4) << 4);
                uint32_t r0, r1, r2, r3;
                LDSM4(r0, r1, r2, r3, a);
                bt[nh * 2 + 0][0] = r0; bt[nh * 2 + 0][1] = r2;
                bt[nh * 2 + 1][0] = r1; bt[nh * 2 + 1][1] = r3;
            }
#pragma unroll
            for (int nf = 0; nf < 4; nf++) {  // 64*t from t, in-register
                bh[nf][0] = (bt[nf][0] << 6) & 0xC0C0C0C0u;
                bh[nf][1] = (bt[nf][1] << 6) & 0xC0C0C0C0u;
            }
            // hi pass: a-operand with 64*t
#pragma unroll
            for (int mf = 0; mf < 4; mf++) {
                uint32_t a = sb + (wm + mf * 16 + ((lane >> 3) & 1) * 8 + (lane & 7)) * 80 +
                             ks * 32 + ((lane >> 4) << 4);
                LDSM4(af[mf][0], af[mf][1], af[mf][2], af[mf][3], a);
            }
#pragma unroll
            for (int mf = 0; mf < 4; mf++)
#pragma unroll
                for (int nf = 0; nf < 4; nf++) IMMA(acc[mf][nf], af[mf], bh[nf]);
            // lo pass: b-operand with t
#pragma unroll
            for (int mf = 0; mf < 4; mf++) {
                uint32_t a = sb + 10240 + (wm + mf * 16 + ((lane >> 3) & 1) * 8 + (lane & 7)) * 80 +
                             ks * 32 + ((lane >> 4) << 4);
                LDSM4(af[mf][0], af[mf][1], af[mf][2], af[mf][3], a);
            }
#pragma unroll
            for (int mf = 0; mf < 4; mf++)
#pragma unroll
                for (int nf = 0; nf < 4; nf++) IMMA(acc[mf][nf], af[mf], bt[nf]);
        }
        __syncthreads();
    }

    if (tid < 128) s_rm[tid] = 0u;
    __syncthreads();
    const float aw = g_scale[sidx];
#pragma unroll
    for (int mf = 0; mf < 4; mf++) {
#pragma unroll
        for (int h2 = 0; h2 < 2; h2++) {
            int rl = wm + mf * 16 + (lane >> 2) + h2 * 8;
            int row = bm + rl;
            float sc = aw * g_s[stIn][row];
#pragma unroll
            for (int nf = 0; nf < 4; nf++) {
                int col = bn + wn + nf * 8 + (lane & 3) * 2;
                size_t o = (size_t)row * Ncols + col;
                float v0 = (float)acc[mf][nf][h2 * 2 + 0] * sc + bias[col];
                float v1 = (float)acc[mf][nf][h2 * 2 + 1] * sc + bias[col + 1];
                if (EPI == EPI_RES) {
                    float2 hp = *(const float2*)&ActOut[o];
                    v0 += hp.x; v1 += hp.y;
                }
                if (EPI == EPI_GELU) { v0 = gelu_f(v0); v1 = gelu_f(v1); }
                float2 w; w.x = v0; w.y = v1;
                if (EPI == EPI_Z) {
                    *(float2*)&Zout[o] = w;
                } else {
                    *(float2*)&ActOut[o] = w;
                    float m = fmaxf(fabsf(v0), fabsf(v1));
                    atomicMax(&s_rm[rl], __float_as_uint(m));
                }
            }
        }
    }
    __syncthreads();
    if (EPI != EPI_Z && tid < 128) atomicMax(&g_rmax[stOut][bm + tid], s_rm[tid]);
}

// ---------------- focus mask ----------------
__global__ void k_focus(const float* __restrict__ h, const float* __restrict__ bm,
                        float* __restrict__ out) {
    int row = blockIdx.x * 8 + (threadIdx.x >> 5);
    int lane = threadIdx.x & 31;
    if (row >= NROWS) return;
    const float* hr = h + (size_t)row * DIMX;
    float sum = 0.0f;
    for (int c = lane; c < DIMX; c += 32) sum += hr[c] * (float)g_wqm[c];
#pragma unroll
    for (int o = 16; o; o >>= 1) sum += __shfl_xor_sync(0xffffffffu, sum, o);
    if (lane == 0) {
        float v = g_scale[6] * sum + bm[0];
        out[row] = 1.0f / (1.0f + expf(-v));
    }
}

// ---------------- launcher ----------------
extern "C" void kernel_launch(void* const* d_in, const int* in_sizes, int n_in,
                              void* d_out, int out_size) {
    const float* x    = (const float*)d_in[0];
    const float* y    = (const float*)d_in[1];
    const float* sp   = (const float*)d_in[2];
    const float* W_in = (const float*)d_in[3];
    const float* b_in = (const float*)d_in[4];
    const float* W1   = (const float*)d_in[5];
    const float* b1   = (const float*)d_in[6];
    const float* W2   = (const float*)d_in[7];
    const float* b2   = (const float*)d_in[8];
    const float* W_z  = (const float*)d_in[9];
    const float* b_z  = (const float*)d_in[10];
    const float* W_m  = (const float*)d_in[11];
    const float* b_m  = (const float*)d_in[12];
    float* out = (float*)d_out;

    void *pA0a, *pA0b, *pha, *phb, *pua, *pub, *ph, *pu;
    void *pwin, *pw1, *pw2, *pwz, *pwm;
    cudaGetSymbolAddress(&pA0a, g_A0a);  cudaGetSymbolAddress(&pA0b, g_A0b);
    cudaGetSymbolAddress(&pha, g_ha);    cudaGetSymbolAddress(&phb, g_hb);
    cudaGetSymbolAddress(&pua, g_ua);    cudaGetSymbolAddress(&pub, g_ub);
    cudaGetSymbolAddress(&ph, g_h);      cudaGetSymbolAddress(&pu, g_u);
    cudaGetSymbolAddress(&pwin, g_wq_in);
    cudaGetSymbolAddress(&pw1, g_wq1);   cudaGetSymbolAddress(&pw2, g_wq2);
    cudaGetSymbolAddress(&pwz, g_wqz);   cudaGetSymbolAddress(&pwm, g_wqm);

    s8* wq_in = (s8*)pwin;
    s8* wq1 = (s8*)pw1;
    s8* wq2 = (s8*)pw2;

    cudaFuncSetAttribute(k_igemm<EPI_H>,    cudaFuncAttributeMaxDynamicSharedMemorySize, 2 * STG);
    cudaFuncSetAttribute(k_igemm<EPI_GELU>, cudaFuncAttributeMaxDynamicSharedMemorySize, 2 * STG);
    cudaFuncSetAttribute(k_igemm<EPI_RES>,  cudaFuncAttributeMaxDynamicSharedMemorySize, 2 * STG);
    cudaFuncSetAttribute(k_igemm<EPI_Z>,    cudaFuncAttributeMaxDynamicSharedMemorySize, 2 * STG);

    k_zero<<<128, 256>>>();

    P7 pa;
    pa.w[0] = W_in;                      pa.n[0] = (long)DIMX * KIN;
    pa.w[1] = W1;                        pa.n[1] = (long)HIDX * DIMX;
    pa.w[2] = W1 + (size_t)HIDX * DIMX;  pa.n[2] = (long)HIDX * DIMX;
    pa.w[3] = W2;                        pa.n[3] = (long)DIMX * HIDX;
    pa.w[4] = W2 + (size_t)DIMX * HIDX;  pa.n[4] = (long)DIMX * HIDX;
    pa.w[5] = W_z;                       pa.n[5] = (long)DIMX * DIMX;
    pa.w[6] = W_m;                       pa.n[6] = (long)DIMX;
    k_abssum7<<<dim3(NPART, 7), 256>>>(pa);
    k_finalize<<<1, 32>>>();

    Q7 qa;
    for (int i = 0; i < 7; i++) { qa.w[i] = pa.w[i]; qa.n[i] = pa.n[i]; }
    qa.q[0] = wq_in;
    qa.q[1] = wq1;
    qa.q[2] = wq1 + (size_t)HIDX * DIMX;
    qa.q[3] = wq2;
    qa.q[4] = wq2 + (size_t)DIMX * HIDX;
    qa.q[5] = (s8*)pwz;
    qa.q[6] = (s8*)pwm;
    k_quant7<<<dim3(2048, 7), 256>>>(qa);

    k_build_a0<<<NROWS, 256>>>(x, y, sp);

    dim3 gD(8, 162), gH(32, 162);

    // h = A0 @ Win^T + b_in        (stage0 -> rmax stage1)
    k_igemm<EPI_H><<<gD, 256, 2 * STG>>>((s8*)pA0a, (s8*)pA0b, wq_in, KIN,
                                         b_in, 0, 0, 1, DIMX, (float*)ph, nullptr);
    k_rowscale<<<(NROWS + 255) / 256, 256>>>(1);
    k_quantact<<<4096, 256>>>((float*)ph, 1, 10, (s8*)pha, (s8*)phb, (size_t)NROWS * DIMX);

    for (int l = 0; l < 2; l++) {
        int sH = 1 + 2 * l, sU = 2 + 2 * l, sO = 3 + 2 * l;
        k_igemm<EPI_GELU><<<gH, 256, 2 * STG>>>(
            (s8*)pha, (s8*)phb, wq1 + (size_t)l * HIDX * DIMX, DIMX,
            b1 + (size_t)l * HIDX, 1 + l, sH, sU, HIDX, (float*)pu, nullptr);
        k_rowscale<<<(NROWS + 255) / 256, 256>>>(sU);
        k_quantact<<<4096, 256>>>((float*)pu, sU, 12, (s8*)pua, (s8*)pub,
                                  (size_t)NROWS * HIDX);
        k_igemm<EPI_RES><<<gD, 256, 2 * STG>>>(
            (s8*)pua, (s8*)pub, wq2 + (size_t)l * DIMX * HIDX, HIDX,
            b2 + (size_t)l * DIMX, 3 + l, sU, sO, DIMX, (float*)ph, nullptr);
        k_rowscale<<<(NROWS + 255) / 256, 256>>>(sO);
        k_quantact<<<4096, 256>>>((float*)ph, sO, 10, (s8*)pha, (s8*)phb,
                                  (size_t)NROWS * DIMX);
    }

    // z = h @ Wz^T + b_z   (straight to d_out)
    k_igemm<EPI_Z><<<gD, 256, 2 * STG>>>((s8*)pha, (s8*)phb, (s8*)pwz, DIMX,
                                         b_z, 5, 5, 0, DIMX, nullptr, out);
    // focus_mask
    k_focus<<<NROWS / 8, 256>>>((const float*)ph, b_m, out + (size_t)NROWS * DIMX);
}

// round 5
// speedup vs baseline: 3.4834x; 3.4834x over previous
#include <cuda_runtime.h>
#include <cuda_fp16.h>
#include <cstdint>

#define NROWS 20736
#define DIMX 1024
#define HIDX 4096
#define KIN  3072

// ---------------- scratch (device globals; no allocs) ----------------
__device__ __align__(16) __half g_A0[(size_t)NROWS * KIN];
__device__ __align__(16) __half g_hx[(size_t)NROWS * DIMX];
__device__ __align__(16) __half g_ux[(size_t)NROWS * HIDX];
__device__ __align__(16) float  g_h [(size_t)NROWS * DIMX];

__device__ __align__(16) __half g_wq_in[DIMX * KIN];
__device__ __align__(16) __half g_wq1[2 * HIDX * DIMX];
__device__ __align__(16) __half g_wq2[2 * DIMX * HIDX];
__device__ __align__(16) __half g_wqz[DIMX * DIMX];
__device__ __align__(16) __half g_wqm[DIMX];

#define NPART 512
__device__ double g_part[8][NPART];
__device__ float  g_scale[8];

// ---------------- prep: scales + quantize (merged launches) ----------------
struct P7 { const float* w[7]; long n[7]; };
struct Q7 { const float* w[7]; __half* q[7]; long n[7]; };

__global__ void k_abssum7(P7 p) {
    int t = blockIdx.y;
    const float* __restrict__ w = p.w[t];
    long n = p.n[t];
    double s = 0.0;
    for (long i = (long)blockIdx.x * blockDim.x + threadIdx.x; i < n;
         i += (long)gridDim.x * blockDim.x)
        s += fabs((double)w[i]);
    __shared__ double sh[256];
    sh[threadIdx.x] = s;
    __syncthreads();
    for (int o = 128; o > 0; o >>= 1) {
        if (threadIdx.x < o) sh[threadIdx.x] += sh[threadIdx.x + o];
        __syncthreads();
    }
    if (threadIdx.x == 0) g_part[t][blockIdx.x] = sh[0];  // fixed slot => deterministic
}

__global__ void k_finalize() {
    int i = threadIdx.x;
    if (i >= 7) return;
    const double cnt[7] = {3145728.0, 4194304.0, 4194304.0, 4194304.0,
                           4194304.0, 1048576.0, 1024.0};
    double s = 0.0;
    for (int j = 0; j < NPART; j++) s += g_part[i][j];
    g_scale[i] = (float)(s / cnt[i]) + 1e-8f;
}

__global__ void k_quant7(Q7 p) {
    int t = blockIdx.y;
    const float* __restrict__ w = p.w[t];
    __half* __restrict__ q = p.q[t];
    long n = p.n[t];
    float a = g_scale[t];
    for (long i = (long)blockIdx.x * blockDim.x + threadIdx.x; i < n;
         i += (long)gridDim.x * blockDim.x) {
        float v = rintf(w[i] / a);           // round-half-even, matches jnp.round
        v = fminf(1.0f, fmaxf(-1.0f, v));
        q[i] = __float2half_rn(v);           // exact: {-1,0,1}
    }
}

// ---------------- concat -> fp16 ----------------
__global__ void k_build_a0(const float* __restrict__ x, const float* __restrict__ y,
                           const float* __restrict__ s) {
    size_t n = (size_t)NROWS * KIN;
    for (size_t i = (size_t)blockIdx.x * blockDim.x + threadIdx.x; i < n;
         i += (size_t)gridDim.x * blockDim.x) {
        size_t row = i / KIN;
        int c = (int)(i % KIN);
        float v = (c < DIMX)     ? x[row * DIMX + c]
                : (c < 2 * DIMX) ? y[row * DIMX + (c - DIMX)]
                                 : s[row * DIMX + (c - 2 * DIMX)];
        g_A0[i] = __float2half_rn(v);
    }
}

// ---------------- GEMM: 128x128x32 fp16 mma.sync, single pass ----------------
__device__ __forceinline__ void cpasync16(void* smem, const void* gmem) {
    unsigned s = (unsigned)__cvta_generic_to_shared(smem);
    asm volatile("cp.async.cg.shared.global [%0], [%1], 16;\n" ::"r"(s), "l"(gmem));
}
__device__ __forceinline__ float gelu_f(float x) {
    return 0.5f * x * (1.0f + erff(x * 0.70710678118654752f));
}

enum { EPI_H = 0, EPI_GELU = 1, EPI_RES = 2, EPI_Z = 3 };

template <int EPI>
__global__ void __launch_bounds__(256, 2)
k_gemm(const __half* __restrict__ A, const __half* __restrict__ Bw, int K,
       const float* __restrict__ bias, int sidx, int Ncols,
       float* __restrict__ Hio, __half* __restrict__ Oh, float* __restrict__ Zout) {
    __shared__ __align__(16) __half sA[2][128][40];
    __shared__ __align__(16) __half sB[2][128][40];
    const int tid = threadIdx.x, lane = tid & 31, wid = tid >> 5;
    const int bm = blockIdx.y * 128, bn = blockIdx.x * 128;
    const int wm = (wid >> 2) * 64, wn = (wid & 3) * 32;

    float acc[4][4][4];
#pragma unroll
    for (int i = 0; i < 4; i++)
#pragma unroll
        for (int j = 0; j < 4; j++)
#pragma unroll
            for (int k = 0; k < 4; k++) acc[i][j][k] = 0.0f;

    const int KT = K / 32;

#define LOAD_TILE(kt, buf)                                                         \
    do {                                                                           \
        int k0 = (kt) * 32;                                                        \
        _Pragma("unroll") for (int i = 0; i < 2; i++) {                            \
            int j = tid + i * 256;                                                 \
            int r = j >> 2, c = j & 3;                                             \
            cpasync16(&sA[buf][r][c * 8], A + (size_t)(bm + r) * K + k0 + c * 8);  \
            cpasync16(&sB[buf][r][c * 8], Bw + (size_t)(bn + r) * K + k0 + c * 8); \
        }                                                                          \
    } while (0)

    LOAD_TILE(0, 0);
    asm volatile("cp.async.commit_group;\n");

    for (int kt = 0; kt < KT; kt++) {
        int buf = kt & 1;
        if (kt + 1 < KT) LOAD_TILE(kt + 1, buf ^ 1);
        asm volatile("cp.async.commit_group;\n");
        asm volatile("cp.async.wait_group 1;\n" ::: "memory");
        __syncthreads();
#pragma unroll
        for (int ks = 0; ks < 2; ks++) {
            uint32_t af[4][4], bf[4][2];
#pragma unroll
            for (int mf = 0; mf < 4; mf++) {
                const __half* p =
                    &sA[buf][wm + mf * 16 + (lane & 15)][ks * 16 + (lane >> 4) * 8];
                unsigned s = (unsigned)__cvta_generic_to_shared(p);
                asm volatile(
                    "ldmatrix.sync.aligned.m8n8.x4.shared.b16 {%0,%1,%2,%3}, [%4];"
                    : "=r"(af[mf][0]), "=r"(af[mf][1]), "=r"(af[mf][2]), "=r"(af[mf][3])
                    : "r"(s));
            }
#pragma unroll
            for (int nh = 0; nh < 2; nh++) {
                const __half* p =
                    &sB[buf][wn + nh * 16 + (lane & 15)][ks * 16 + (lane >> 4) * 8];
                unsigned s = (unsigned)__cvta_generic_to_shared(p);
                uint32_t r0, r1, r2, r3;
                asm volatile(
                    "ldmatrix.sync.aligned.m8n8.x4.shared.b16 {%0,%1,%2,%3}, [%4];"
                    : "=r"(r0), "=r"(r1), "=r"(r2), "=r"(r3)
                    : "r"(s));
                bf[nh * 2 + 0][0] = r0; bf[nh * 2 + 0][1] = r2;
                bf[nh * 2 + 1][0] = r1; bf[nh * 2 + 1][1] = r3;
            }
#pragma unroll
            for (int mf = 0; mf < 4; mf++)
#pragma unroll
                for (int nf = 0; nf < 4; nf++)
                    asm volatile(
                        "mma.sync.aligned.m16n8k16.row.col.f32.f16.f16.f32 "
                        "{%0,%1,%2,%3},{%4,%5,%6,%7},{%8,%9},{%0,%1,%2,%3};"
                        : "+f"(acc[mf][nf][0]), "+f"(acc[mf][nf][1]),
                          "+f"(acc[mf][nf][2]), "+f"(acc[mf][nf][3])
                        : "r"(af[mf][0]), "r"(af[mf][1]), "r"(af[mf][2]), "r"(af[mf][3]),
                          "r"(bf[nf][0]), "r"(bf[nf][1]));
        }
        __syncthreads();
    }

    const float a_s = g_scale[sidx];
#pragma unroll
    for (int mf = 0; mf < 4; mf++) {
#pragma unroll
        for (int nf = 0; nf < 4; nf++) {
            int col = bn + wn + nf * 8 + (lane & 3) * 2;
            float b0 = bias[col], b1 = bias[col + 1];
#pragma unroll
            for (int h2 = 0; h2 < 2; h2++) {
                int row = bm + wm + mf * 16 + (lane >> 2) + h2 * 8;
                size_t o = (size_t)row * Ncols + col;
                float v0 = fmaf(a_s, acc[mf][nf][h2 * 2 + 0], b0);
                float v1 = fmaf(a_s, acc[mf][nf][h2 * 2 + 1], b1);
                if (EPI == EPI_RES) {
                    float2 hp = *(const float2*)&Hio[o];
                    v0 += hp.x; v1 += hp.y;
                }
                if (EPI == EPI_GELU) { v0 = gelu_f(v0); v1 = gelu_f(v1); }
                if (EPI == EPI_H || EPI == EPI_RES) {
                    float2 w; w.x = v0; w.y = v1;
                    *(float2*)&Hio[o] = w;
                }
                if (EPI == EPI_Z) {
                    float2 w; w.x = v0; w.y = v1;
                    *(float2*)&Zout[o] = w;
                } else {
                    __half2 ph;
                    ph.x = __float2half_rn(v0);
                    ph.y = __float2half_rn(v1);
                    *(__half2*)&Oh[o] = ph;
                }
            }
        }
    }
#undef LOAD_TILE
}

// ---------------- focus mask: one warp per row ----------------
__global__ void k_focus(const float* __restrict__ h, const float* __restrict__ bm,
                        float* __restrict__ out) {
    int row = blockIdx.x * 8 + (threadIdx.x >> 5);
    int lane = threadIdx.x & 31;
    if (row >= NROWS) return;
    const float* hr = h + (size_t)row * DIMX;
    float sum = 0.0f;
    for (int c = lane; c < DIMX; c += 32) sum += hr[c] * __half2float(g_wqm[c]);
#pragma unroll
    for (int o = 16; o; o >>= 1) sum += __shfl_xor_sync(0xffffffffu, sum, o);
    if (lane == 0) {
        float v = g_scale[6] * sum + bm[0];
        out[row] = 1.0f / (1.0f + expf(-v));
    }
}

// ---------------- launcher ----------------
extern "C" void kernel_launch(void* const* d_in, const int* in_sizes, int n_in,
                              void* d_out, int out_size) {
    const float* x    = (const float*)d_in[0];
    const float* y    = (const float*)d_in[1];
    const float* sp   = (const float*)d_in[2];
    const float* W_in = (const float*)d_in[3];
    const float* b_in = (const float*)d_in[4];
    const float* W1   = (const float*)d_in[5];
    const float* b1   = (const float*)d_in[6];
    const float* W2   = (const float*)d_in[7];
    const float* b2   = (const float*)d_in[8];
    const float* W_z  = (const float*)d_in[9];
    const float* b_z  = (const float*)d_in[10];
    const float* W_m  = (const float*)d_in[11];
    const float* b_m  = (const float*)d_in[12];
    float* out = (float*)d_out;

    void *pA0, *phx, *pux, *ph, *pwin, *pw1, *pw2, *pwz, *pwm;
    cudaGetSymbolAddress(&pA0, g_A0);
    cudaGetSymbolAddress(&phx, g_hx);
    cudaGetSymbolAddress(&pux, g_ux);
    cudaGetSymbolAddress(&ph, g_h);
    cudaGetSymbolAddress(&pwin, g_wq_in);
    cudaGetSymbolAddress(&pw1, g_wq1);
    cudaGetSymbolAddress(&pw2, g_wq2);
    cudaGetSymbolAddress(&pwz, g_wqz);
    cudaGetSymbolAddress(&pwm, g_wqm);

    __half* wq_in = (__half*)pwin;
    __half* wq1   = (__half*)pw1;
    __half* wq2   = (__half*)pw2;

    // 1) per-tensor scales (deterministic two-pass fp64 mean), merged
    P7 pa;
    pa.w[0] = W_in;                      pa.n[0] = (long)DIMX * KIN;
    pa.w[1] = W1;                        pa.n[1] = (long)HIDX * DIMX;
    pa.w[2] = W1 + (size_t)HIDX * DIMX;  pa.n[2] = (long)HIDX * DIMX;
    pa.w[3] = W2;                        pa.n[3] = (long)DIMX * HIDX;
    pa.w[4] = W2 + (size_t)DIMX * HIDX;  pa.n[4] = (long)DIMX * HIDX;
    pa.w[5] = W_z;                       pa.n[5] = (long)DIMX * DIMX;
    pa.w[6] = W_m;                       pa.n[6] = (long)DIMX;
    k_abssum7<<<dim3(NPART, 7), 256>>>(pa);
    k_finalize<<<1, 32>>>();

    // 2) ternary-quantize weights (exact fp16 {-1,0,1}), merged
    Q7 qa;
    for (int i = 0; i < 7; i++) { qa.w[i] = pa.w[i]; qa.n[i] = pa.n[i]; }
    qa.q[0] = wq_in;
    qa.q[1] = wq1;
    qa.q[2] = wq1 + (size_t)HIDX * DIMX;
    qa.q[3] = wq2;
    qa.q[4] = wq2 + (size_t)DIMX * HIDX;
    qa.q[5] = (__half*)pwz;
    qa.q[6] = (__half*)pwm;
    k_quant7<<<dim3(2048, 7), 256>>>(qa);

    // 3) concat inputs -> fp16
    k_build_a0<<<8192, 256>>>(x, y, sp);

    dim3 gD(DIMX / 128, NROWS / 128);   // (8, 162)
    dim3 gH(HIDX / 128, NROWS / 128);   // (32, 162)

    // 4) h = A0 @ Wq_in^T + b_in
    k_gemm<EPI_H><<<gD, 256>>>((__half*)pA0, wq_in, KIN, b_in, 0, DIMX,
                               (float*)ph, (__half*)phx, nullptr);
    // 5) residual BitMLP blocks
    for (int l = 0; l < 2; l++) {
        k_gemm<EPI_GELU><<<gH, 256>>>(
            (__half*)phx, wq1 + (size_t)l * HIDX * DIMX, DIMX,
            b1 + (size_t)l * HIDX, 1 + l, HIDX, nullptr, (__half*)pux, nullptr);
        k_gemm<EPI_RES><<<gD, 256>>>(
            (__half*)pux, wq2 + (size_t)l * DIMX * HIDX, HIDX,
            b2 + (size_t)l * DIMX, 3 + l, DIMX, (float*)ph, (__half*)phx, nullptr);
    }
    // 6) z = h @ Wq_z^T + b_z   (straight to d_out)
    k_gemm<EPI_Z><<<gD, 256>>>((__half*)phx, (__half*)pwz, DIMX, b_z, 5, DIMX,
                               nullptr, nullptr, out);
    // 7) focus_mask = sigmoid(h @ Wq_m^T + b_m)
    k_focus<<<NROWS / 8, 256>>>((const float*)ph, b_m, out + (size_t)NROWS * DIMX);
}